// round 13
// baseline (speedup 1.0000x reference)
#include <cuda_runtime.h>
#include <cuda_fp16.h>
#include <mma.h>
using namespace nvcuda;

#define BB 4
#define SS 512
#define HH 256
#define H4 (HH / 4)        // 64 groups of 4 h-elements

// Scratch (allocation-free rule -> __device__ globals)
__device__ __half g_h16 [BB * SS * HH];      // h in fp16
__device__ __half g_wt16 [HH * HH];          // Wt in fp16
__device__ __half g_wtp16[HH * HH];          // Wtp in fp16
__device__ __half g_ht_h[BB * SS * HH];      // [bt][h]  ht + b_h, half
__device__ uint2  g_htpT[BB * H4 * SS];      // [b][h4][tp] packed halves of htp
__device__ __half g_p16[BB * SS * SS];       // unnormalized exp(sigmoid(score)), fp16
__device__ float  g_rsump[16][BB * SS];      // per-tp-tile partial row sums

__device__ __forceinline__ float tanh_fast(float x) {
    float y; asm("tanh.approx.f32 %0, %1;" : "=f"(y) : "f"(x)); return y;
}
__device__ __forceinline__ unsigned tanh2u(unsigned x) {
    unsigned y; asm("tanh.approx.f16x2 %0, %1;" : "=r"(y) : "r"(x)); return y;
}
__device__ __forceinline__ __half2 u2h(unsigned x) { return *reinterpret_cast<__half2*>(&x); }
__device__ __forceinline__ unsigned h2u(__half2 x) { return *reinterpret_cast<unsigned*>(&x); }

// ---------------------------------------------------------------------------
// Stage 0: fp32 -> fp16 conversion of h, Wt, Wtp (vectorized).
// ---------------------------------------------------------------------------
__global__ void __launch_bounds__(256)
convert_kernel(const float* __restrict__ h,
               const float* __restrict__ Wt,
               const float* __restrict__ Wtp)
{
    const int g      = blockIdx.x * blockDim.x + threadIdx.x;
    const int stride = gridDim.x * blockDim.x;

    const int nH = BB * SS * HH / 4;
    const int nW = HH * HH / 4;

    uint2* h16  = reinterpret_cast<uint2*>(g_h16);
    uint2* wt16 = reinterpret_cast<uint2*>(g_wt16);
    uint2* wp16 = reinterpret_cast<uint2*>(g_wtp16);

    for (int i = g; i < nH; i += stride) {
        const float4 v = reinterpret_cast<const float4*>(h)[i];
        uint2 o;
        o.x = h2u(__floats2half2_rn(v.x, v.y));
        o.y = h2u(__floats2half2_rn(v.z, v.w));
        h16[i] = o;
    }
    for (int i = g; i < nW; i += stride) {
        const float4 a = reinterpret_cast<const float4*>(Wt)[i];
        const float4 b = reinterpret_cast<const float4*>(Wtp)[i];
        uint2 oa, ob;
        oa.x = h2u(__floats2half2_rn(a.x, a.y));
        oa.y = h2u(__floats2half2_rn(a.z, a.w));
        ob.x = h2u(__floats2half2_rn(b.x, b.y));
        ob.y = h2u(__floats2half2_rn(b.z, b.w));
        wt16[i] = oa;
        wp16[i] = ob;
    }
}

// ---------------------------------------------------------------------------
// Stage 1: projections on tensor cores (wmma fp16, fp32 accumulate).
// ---------------------------------------------------------------------------
__global__ void __launch_bounds__(256)
proj_wmma_kernel(const float* __restrict__ bh)
{
    const int mt   = blockIdx.x;        // 0..31
    const int nt   = blockIdx.y;        // 0..3
    const int wsel = blockIdx.z;        // 0: Wt, 1: Wtp
    const __half* __restrict__ A = g_h16;
    const __half* __restrict__ B = wsel ? g_wtp16 : g_wt16;

    const int warp = threadIdx.x >> 5;
    const int wm   = warp >> 1;
    const int wn   = warp & 1;
    const int row0 = mt * 64 + wm * 16;
    const int col0 = nt * 64 + wn * 32;

    wmma::fragment<wmma::accumulator, 16, 16, 16, float> c0, c1;
    wmma::fill_fragment(c0, 0.f);
    wmma::fill_fragment(c1, 0.f);

#pragma unroll 4
    for (int k = 0; k < HH; k += 16) {
        wmma::fragment<wmma::matrix_a, 16, 16, 16, __half, wmma::row_major> a;
        wmma::fragment<wmma::matrix_b, 16, 16, 16, __half, wmma::row_major> b0, b1;
        wmma::load_matrix_sync(a,  A + (size_t)row0 * HH + k, HH);
        wmma::load_matrix_sync(b0, B + (size_t)k * HH + col0,      HH);
        wmma::load_matrix_sync(b1, B + (size_t)k * HH + col0 + 16, HH);
        wmma::mma_sync(c0, a, b0, c0);
        wmma::mma_sync(c1, a, b1, c1);
    }

    __shared__ float cs[64][68];
    wmma::store_matrix_sync(&cs[wm * 16][wn * 32],      c0, 68, wmma::mem_row_major);
    wmma::store_matrix_sync(&cs[wm * 16][wn * 32 + 16], c1, 68, wmma::mem_row_major);
    __syncthreads();

    const int tid = threadIdx.x;
    if (wsel == 0) {
        for (int e = tid; e < 64 * 64; e += 256) {
            const int r = e >> 6, c = e & 63;
            const int row = mt * 64 + r;
            const int col = nt * 64 + c;
            g_ht_h[(size_t)row * HH + col] = __float2half(cs[r][c] + bh[col]);
        }
    } else {
        __half* htpT = reinterpret_cast<__half*>(g_htpT);
        for (int e = tid; e < 64 * 64; e += 256) {
            const int r = e >> 6, c = e & 63;
            const int row = mt * 64 + r;          // = bt
            const int col = nt * 64 + c;
            const int b   = row >> 9;
            const int tp  = row & (SS - 1);
            htpT[(((size_t)b * H4 + (col >> 2)) * SS + tp) * 4 + (col & 3)] =
                __float2half(cs[r][c]);
        }
    }
}

// ---------------------------------------------------------------------------
// Stage 2: score map. 32 rows/block (4 rows/warp), grid (16 tp-tiles, 64).
// Also emits per-tile partial row sums (g_rsump) for the out kernel.
// ---------------------------------------------------------------------------
__global__ void __launch_bounds__(256)
score_kernel(const float* __restrict__ Wa,
             const float* __restrict__ ba)
{
    const int bt0 = blockIdx.y * 32;        // 32 rows, one batch (32 | 512)
    const int b   = bt0 >> 9;
    const int tid = threadIdx.x;
    const int w   = tid >> 5;
    const int lane= tid & 31;

    __shared__ uint4 su[32][H4];            // {ht01, ht23, wa01, wa23}  32KB

    for (int e = tid; e < 32 * H4; e += 256) {
        const int t  = e >> 6;
        const int h4 = e & 63;
        const uint2 ht4 = reinterpret_cast<const uint2*>(g_ht_h)[(bt0 + t) * (HH / 4) + h4];
        const float4 wa4 = reinterpret_cast<const float4*>(Wa)[h4];
        su[t][h4] = make_uint4(ht4.x, ht4.y,
                               h2u(__floats2half2_rn(wa4.x, wa4.y)),
                               h2u(__floats2half2_rn(wa4.z, wa4.w)));
    }
    __syncthreads();

    const float bav = ba[0];
    const int   tp  = blockIdx.x * 32 + lane;
    const int   r0  = 4 * w;                // warp owns rows r0..r0+3
    const uint2* hp = g_htpT + (size_t)b * H4 * SS + tp;
    const uint4* s0 = su[r0 + 0];
    const uint4* s1 = su[r0 + 1];
    const uint4* s2 = su[r0 + 2];
    const uint4* s3 = su[r0 + 3];

    const __half2 z = __floats2half2_rn(0.f, 0.f);
    float   fa[4]  = {0.f, 0.f, 0.f, 0.f};
    __half2 acc[4] = {z, z, z, z};

#pragma unroll 1
    for (int hb = 0; hb < 16; ++hb) {       // fold to fp32 every 4 h4
#pragma unroll
        for (int j = 0; j < 4; ++j) {
            const int h4 = hb * 4 + j;
            const uint2 x  = hp[(size_t)h4 * SS];
            const __half2 xa = u2h(x.x), xb = u2h(x.y);
            const uint4 u0 = s0[h4];
            const uint4 u1 = s1[h4];
            const uint4 u2 = s2[h4];
            const uint4 u3 = s3[h4];
            acc[0] = __hfma2(u2h(u0.z), u2h(tanh2u(h2u(__hadd2(u2h(u0.x), xa)))), acc[0]);
            acc[0] = __hfma2(u2h(u0.w), u2h(tanh2u(h2u(__hadd2(u2h(u0.y), xb)))), acc[0]);
            acc[1] = __hfma2(u2h(u1.z), u2h(tanh2u(h2u(__hadd2(u2h(u1.x), xa)))), acc[1]);
            acc[1] = __hfma2(u2h(u1.w), u2h(tanh2u(h2u(__hadd2(u2h(u1.y), xb)))), acc[1]);
            acc[2] = __hfma2(u2h(u2.z), u2h(tanh2u(h2u(__hadd2(u2h(u2.x), xa)))), acc[2]);
            acc[2] = __hfma2(u2h(u2.w), u2h(tanh2u(h2u(__hadd2(u2h(u2.y), xb)))), acc[2]);
            acc[3] = __hfma2(u2h(u3.z), u2h(tanh2u(h2u(__hadd2(u2h(u3.x), xa)))), acc[3]);
            acc[3] = __hfma2(u2h(u3.w), u2h(tanh2u(h2u(__hadd2(u2h(u3.y), xb)))), acc[3]);
        }
#pragma unroll
        for (int r = 0; r < 4; ++r) {
            const float2 f = __half22float2(acc[r]);
            fa[r] += f.x + f.y;
            acc[r] = z;
        }
    }

#pragma unroll
    for (int r = 0; r < 4; ++r) {
        const float s = fa[r] + bav;
        float p = __expf(0.5f * tanh_fast(0.5f * s) + 0.5f);
        g_p16[(size_t)(bt0 + r0 + r) * SS + tp] = __float2half(p);
        // partial row sum over this block's 32 tp
#pragma unroll
        for (int off = 16; off > 0; off >>= 1)
            p += __shfl_xor_sync(0xffffffffu, p, off);
        if (lane == 0) g_rsump[blockIdx.x][bt0 + r0 + r] = p;
    }
}

// ---------------------------------------------------------------------------
// Stage 3: output GEMM on tensor cores, 32-row tiles, grid (16, 4, BB).
//  Phase 1: rinv[32] = 1 / sum of 16 partials (fixed order, deterministic).
//  Phase 2: wts slice (32 rows x 128 cols) = p16 * rinv.
//  Phase 3: wmma GEMM (8 warps = 2x4 fragments), epilogue scales by rinv.
// ---------------------------------------------------------------------------
__global__ void __launch_bounds__(256)
out_wmma_kernel(float* __restrict__ out,
                float* __restrict__ wts)
{
    const int mt = blockIdx.x;          // 0..15 (32-row tile)
    const int nt = blockIdx.y;          // 0..3  (64-col tile)
    const int b  = blockIdx.z;          // batch

    const __half* __restrict__ A = g_p16 + (size_t)b * SS * SS;   // [t][tp]
    const __half* __restrict__ B = g_h16 + (size_t)b * SS * HH;   // [tp][k]

    const int tid  = threadIdx.x;
    const int warp = tid >> 5;

    __shared__ float rinv[32];
    __shared__ float cs[32][68];

    // Phase 1: rinv from score-kernel partials.
    if (tid < 32) {
        const int row = b * SS + mt * 32 + tid;
        float s = 0.f;
#pragma unroll
        for (int c = 0; c < 16; ++c) s += g_rsump[c][row];
        rinv[tid] = 1.0f / s;
    }
    __syncthreads();

    // Phase 2: normalized weights, this block's 128-column slice.
    if (wts) {
        for (int e = tid; e < 32 * 32; e += 256) {
            const int r  = e >> 5;           // local row
            const int c  = e & 31;           // uint2 index within slice
            const int row = mt * 32 + r;
            const uint2 v = reinterpret_cast<const uint2*>(
                                A + (size_t)row * SS + nt * 128)[c];
            const float2 f0 = __half22float2(u2h(v.x));
            const float2 f1 = __half22float2(u2h(v.y));
            const float sc = rinv[r];
            float4 o;
            o.x = f0.x * sc; o.y = f0.y * sc; o.z = f1.x * sc; o.w = f1.y * sc;
            reinterpret_cast<float4*>(
                wts + (size_t)(b * SS + row) * SS + nt * 128)[c] = o;
        }
    }

    // Phase 3: GEMM. 8 warps -> 2 row-frags x 4 col-frags.
    const int wm   = warp >> 2;          // 0..1
    const int wn   = warp & 3;           // 0..3
    const int row0 = mt * 32 + wm * 16;
    const int col0 = nt * 64 + wn * 16;

    wmma::fragment<wmma::accumulator, 16, 16, 16, float> c0;
    wmma::fill_fragment(c0, 0.f);

#pragma unroll 4
    for (int k = 0; k < SS; k += 16) {
        wmma::fragment<wmma::matrix_a, 16, 16, 16, __half, wmma::row_major> a;
        wmma::fragment<wmma::matrix_b, 16, 16, 16, __half, wmma::row_major> bf;
        wmma::load_matrix_sync(a,  A + (size_t)row0 * SS + k, SS);
        wmma::load_matrix_sync(bf, B + (size_t)k * HH + col0, HH);
        wmma::mma_sync(c0, a, bf, c0);
    }

    wmma::store_matrix_sync(&cs[wm * 16][wn * 16], c0, 68, wmma::mem_row_major);
    __syncthreads();

    for (int e = tid; e < 32 * 64; e += 256) {
        const int r = e >> 6, c = e & 63;
        const int bt  = b * SS + mt * 32 + r;
        const int col = nt * 64 + c;
        out[(size_t)bt * HH + col] = cs[r][c] * rinv[r];
    }
}

// ---------------------------------------------------------------------------
extern "C" void kernel_launch(void* const* d_in, const int* in_sizes, int n_in,
                              void* d_out, int out_size)
{
    const float* h   = (const float*)d_in[0];
    const float* Wt  = (const float*)d_in[1];
    const float* Wtp = (const float*)d_in[2];
    const float* bh  = (const float*)d_in[3];
    const float* Wa  = (const float*)d_in[4];
    const float* ba  = (const float*)d_in[5];

    float* out = (float*)d_out;
    float* wts = nullptr;
    const int nOut = BB * SS * HH;   // 524288
    const int nW   = BB * SS * SS;   // 1048576
    if (out_size >= nOut + nW) wts = out + nOut;

    convert_kernel<<<256, 256>>>(h, Wt, Wtp);
    proj_wmma_kernel<<<dim3(32, 4, 2), 256>>>(bh);
    score_kernel<<<dim3(SS / 32, BB * SS / 32), 256>>>(Wa, ba);
    out_wmma_kernel<<<dim3(16, 4, BB), 256>>>(out, wts);
}